// round 4
// baseline (speedup 1.0000x reference)
#include <cuda_runtime.h>
#include <cuda_bf16.h>
#include <math.h>

#define BB 8
#define SS 2048
#define DIMV 240
#define NTOK (BB*SS)          // 16384
#define NEXP 8
#define NDEPTH 8
#define LATENTV 8
#define LOWD 80
#define LNEPS 1e-5f
#define PI_F 3.14159265358979323846f

// ------------------------- device scratch ----------------------------------
__device__ float g_h[(size_t)NTOK * DIMV];
__device__ float g_part[2][(size_t)NTOK * DIMV];
__device__ int   g_cnt[NDEPTH][NEXP];
__device__ int   g_list_tok[NEXP][NTOK];
__device__ float g_list_w[NEXP][NTOK];
__device__ int   g_list_k[NEXP][NTOK];
__device__ int   g_route_e[NTOK * 2];
__device__ float g_route_w[NTOK * 2];
__device__ float g_ce[240 * DIMV];
__device__ float g_se[240 * DIMV];

// ------------------------- f32x2 helpers ------------------------------------
__device__ __forceinline__ void fma2(unsigned long long &d,
                                     unsigned long long a,
                                     unsigned long long b) {
    asm("fma.rn.f32x2 %0, %1, %2, %0;" : "+l"(d) : "l"(a), "l"(b));
}
__device__ __forceinline__ unsigned long long pack2(float a) {
    unsigned long long r;
    asm("mov.b64 %0, {%1, %1};" : "=l"(r) : "f"(a));
    return r;
}
__device__ __forceinline__ void unpack2(unsigned long long v, float &lo, float &hi) {
    asm("mov.b64 {%0, %1}, %2;" : "=f"(lo), "=f"(hi) : "l"(v));
}

// ------------------------- setup: emb tables + counter zero -----------------
__global__ void setup_kernel(const float* __restrict__ roots,
                             const float* __restrict__ projW) {
    int s = blockIdx.x;
    int d = threadIdx.x;
    int j = d % LOWD;
    float emb = 0.f;
#pragma unroll
    for (int i = 0; i < LATENTV; i++)
        emb += roots[s * LATENTV + i] * projW[i * LOWD + j];
    g_ce[s * DIMV + d] = cosf(emb);
    g_se[s * DIMV + d] = sinf(emb);
    if (blockIdx.x == 0 && d < NDEPTH * NEXP)
        ((int*)g_cnt)[d] = 0;
}

// ------------------------- cycle block --------------------------------------
__global__ void cycle_kernel(const float* __restrict__ x,
                             const int* __restrict__ step) {
    __shared__ float s_x1[DIMV];
    __shared__ float s_se[DIMV];
    __shared__ float s_pump;
    int t = blockIdx.x;
    int d = threadIdx.x;
    int r = (t % SS) % 240;
    if (d == 0) s_pump = 0.8f * sinf((float)(*step) * 0.006f * 2.0f * PI_F);
    float ce = g_ce[r * DIMV + d];
    float se = g_se[r * DIMV + d];
    s_se[d] = se;
    __syncthreads();
    float x1 = x[(size_t)t * DIMV + d] * (ce + s_pump);
    s_x1[d] = x1;
    __syncthreads();
    int dm1 = (d + DIMV - 1) % DIMV;
    int dm2 = (d + DIMV - 2) % DIMV;
    float h = (s_x1[d]
             + s_x1[dm1] * se
             + s_x1[dm2] * s_se[dm1] * ce) * (1.0f / 3.0f);
    g_h[(size_t)t * DIMV + d] = h;
}

// ------------------------- gate helper (warp; h in registers) ---------------
__device__ __forceinline__ void gate_from_regs(const float hh[8],
                                               const float* __restrict__ gW,
                                               const float* __restrict__ gb,
                                               int L, int tok, int lane) {
    float acc[8];
#pragma unroll
    for (int e = 0; e < 8; e++) acc[e] = 0.f;
#pragma unroll
    for (int jq = 0; jq < 8; jq++) {
        int d = lane + 32 * jq;
        if (d < DIMV) {
            float hv = hh[jq];
            float4 w0 = *(const float4*)&gW[d * 8];
            float4 w1 = *(const float4*)&gW[d * 8 + 4];
            acc[0] += hv * w0.x; acc[1] += hv * w0.y;
            acc[2] += hv * w0.z; acc[3] += hv * w0.w;
            acc[4] += hv * w1.x; acc[5] += hv * w1.y;
            acc[6] += hv * w1.z; acc[7] += hv * w1.w;
        }
    }
#pragma unroll
    for (int e = 0; e < 8; e++)
#pragma unroll
        for (int o = 16; o > 0; o >>= 1)
            acc[e] += __shfl_xor_sync(0xffffffffu, acc[e], o);

    if (lane == 0) {
        float l[8];
#pragma unroll
        for (int e = 0; e < 8; e++) l[e] = acc[e] + gb[e];
        int e0 = 0; float b0 = l[0];
#pragma unroll
        for (int q = 1; q < 8; q++)
            if (l[q] > b0) { b0 = l[q]; e0 = q; }
        int e1 = -1; float b1 = -1e30f;
#pragma unroll
        for (int q = 0; q < 8; q++)
            if (q != e0 && l[q] > b1) { b1 = l[q]; e1 = q; }

        float w0 = 1.0f / (1.0f + expf(b1 - b0));
        float w1 = 1.0f - w0;

        int p0 = atomicAdd(&g_cnt[L][e0], 1);
        g_list_tok[e0][p0] = tok; g_list_w[e0][p0] = w0; g_list_k[e0][p0] = 0;
        int p1 = atomicAdd(&g_cnt[L][e1], 1);
        g_list_tok[e1][p1] = tok; g_list_w[e1][p1] = w1; g_list_k[e1][p1] = 1;

        g_route_e[tok * 2 + 0] = e0; g_route_e[tok * 2 + 1] = e1;
        g_route_w[tok * 2 + 0] = w0; g_route_w[tok * 2 + 1] = w1;
    }
}

// ------------------------- gate from g_h (layer 0) ---------------------------
__global__ void gate_kernel(const float* __restrict__ gW,
                            const float* __restrict__ gb, int L) {
    int warp = threadIdx.x >> 5;
    int lane = threadIdx.x & 31;
    int tok  = blockIdx.x * 8 + warp;
    const float* h = g_h + (size_t)tok * DIMV;
    float hh[8];
#pragma unroll
    for (int jq = 0; jq < 8; jq++) {
        int d = lane + 32 * jq;
        hh[jq] = (d < DIMV) ? h[d] : 0.f;
    }
    gate_from_regs(hh, gW, gb, L, tok, lane);
}

// ------------------------- grouped expert GEMM (8x8 f32x2) ------------------
#define MT 128
__global__ __launch_bounds__(256, 1)
void moe_gemm_kernel(const float* __restrict__ eW, int L) {
    int e = blockIdx.y;
    int cnt = g_cnt[L][e];
    int base = blockIdx.x * MT;
    if (base >= cnt) return;
    int mr = min(MT, cnt - base);

    __shared__ __align__(16) float As_t[16][MT + 4];   // [k][token]
    __shared__ __align__(16) float Bs[16][256];        // [k][col], 240..255 pad
    __shared__ int   s_tok[MT];
    __shared__ float s_w[MT];
    __shared__ int   s_k[MT];

    int tid = threadIdx.x;             // 256
    if (tid < MT) {
        if (tid < mr) {
            s_tok[tid] = g_list_tok[e][base + tid];
            s_w[tid]   = g_list_w[e][base + tid];
            s_k[tid]   = g_list_k[e][base + tid];
        } else {
            s_tok[tid] = 0; s_w[tid] = 0.f; s_k[tid] = 0;
        }
    }
    // zero pad columns (written once; never overwritten)
    Bs[tid >> 4][240 + (tid & 15)] = 0.f;
    __syncthreads();   // <-- s_tok/s_w/s_k and pad must be visible to all

    int tx = tid & 15;                 // col-pair group 0..15
    int ty = tid >> 4;                 // row group 0..15 (rows ty*8..ty*8+7)

    unsigned long long acc[8][8];
#pragma unroll
    for (int i = 0; i < 8; i++)
#pragma unroll
        for (int jq = 0; jq < 8; jq++) acc[i][jq] = 0ull;

    const float* W = eW + (size_t)e * DIMV * DIMV;

    int g_rr = tid >> 1;               // A-gather: token row 0..127
    int g_c8 = (tid & 1) * 8;          // which 8 of the 16 k's

    for (int k0 = 0; k0 < DIMV; k0 += 16) {
        // gather A slice 128x16 -> As_t[k][token]
        {
            float4 v0, v1;
            if (g_rr < mr) {
                const float* src = &g_h[(size_t)s_tok[g_rr] * DIMV + k0 + g_c8];
                v0 = *(const float4*)src;
                v1 = *(const float4*)(src + 4);
            } else {
                v0 = make_float4(0.f, 0.f, 0.f, 0.f);
                v1 = v0;
            }
            As_t[g_c8 + 0][g_rr] = v0.x; As_t[g_c8 + 1][g_rr] = v0.y;
            As_t[g_c8 + 2][g_rr] = v0.z; As_t[g_c8 + 3][g_rr] = v0.w;
            As_t[g_c8 + 4][g_rr] = v1.x; As_t[g_c8 + 5][g_rr] = v1.y;
            As_t[g_c8 + 6][g_rr] = v1.z; As_t[g_c8 + 7][g_rr] = v1.w;
        }
        // load B slice 16x240 via float4 (960 float4s)
        for (int i = tid; i < 960; i += 256) {
            int rr = i / 60, cc = i - rr * 60;
            *(float4*)&Bs[rr][cc * 4] =
                *(const float4*)&W[(size_t)(k0 + rr) * DIMV + cc * 4];
        }
        __syncthreads();

#pragma unroll
        for (int dk = 0; dk < 16; dk++) {
            float4 a0 = *(const float4*)&As_t[dk][ty * 8];
            float4 a1 = *(const float4*)&As_t[dk][ty * 8 + 4];
            unsigned long long a2[8];
            a2[0] = pack2(a0.x); a2[1] = pack2(a0.y);
            a2[2] = pack2(a0.z); a2[3] = pack2(a0.w);
            a2[4] = pack2(a1.x); a2[5] = pack2(a1.y);
            a2[6] = pack2(a1.z); a2[7] = pack2(a1.w);
            unsigned long long bv[8];
#pragma unroll
            for (int jq = 0; jq < 8; jq++)
                bv[jq] = *(const unsigned long long*)&Bs[dk][(tx + 16 * jq) * 2];
#pragma unroll
            for (int i = 0; i < 8; i++)
#pragma unroll
                for (int jq = 0; jq < 8; jq++)
                    fma2(acc[i][jq], a2[i], bv[jq]);
        }
        __syncthreads();
    }

#pragma unroll
    for (int i = 0; i < 8; i++) {
        int rr = ty * 8 + i;
        if (rr < mr) {
            float w = s_w[rr];
            float* dst = &g_part[s_k[rr]][(size_t)s_tok[rr] * DIMV];
#pragma unroll
            for (int jq = 0; jq < 8; jq++) {
                int P = tx + 16 * jq;
                if (P < 120) {
                    float lo, hi;
                    unpack2(acc[i][jq], lo, hi);
                    float2 o; o.x = w * lo; o.y = w * hi;
                    *(float2*)&dst[2 * P] = o;
                }
            }
        }
    }
}

// ------------- fused: epilogue(L) [+ gate(L+1) if DO_GATE] -------------------
template<int DO_GATE>
__global__ void epi_gate_kernel(const float* __restrict__ eb,     // [E,240]
                                const float* __restrict__ gamma,
                                const float* __restrict__ beta,
                                const float* __restrict__ gW,     // layer L+1
                                const float* __restrict__ gb,
                                int Lnext) {
    int warp = threadIdx.x >> 5;
    int lane = threadIdx.x & 31;
    int tok  = blockIdx.x * 8 + warp;

    int   e0 = g_route_e[tok * 2 + 0], e1 = g_route_e[tok * 2 + 1];
    float w0 = g_route_w[tok * 2 + 0], w1 = g_route_w[tok * 2 + 1];

    const float* p0 = &g_part[0][(size_t)tok * DIMV];
    const float* p1 = &g_part[1][(size_t)tok * DIMV];

    float v[8];
    float sum = 0.f;
#pragma unroll
    for (int jq = 0; jq < 8; jq++) {
        int d = lane + 32 * jq;
        if (d < DIMV) {
            v[jq] = p0[d] + p1[d] + w0 * eb[e0 * DIMV + d] + w1 * eb[e1 * DIMV + d];
            sum += v[jq];
        } else v[jq] = 0.f;
    }
#pragma unroll
    for (int o = 16; o > 0; o >>= 1) sum += __shfl_xor_sync(0xffffffffu, sum, o);
    float mean = sum * (1.0f / DIMV);

    float vs = 0.f;
#pragma unroll
    for (int jq = 0; jq < 8; jq++) {
        int d = lane + 32 * jq;
        if (d < DIMV) { float c = v[jq] - mean; vs += c * c; }
    }
#pragma unroll
    for (int o = 16; o > 0; o >>= 1) vs += __shfl_xor_sync(0xffffffffu, vs, o);
    float inv = 1.0f / sqrtf(vs * (1.0f / DIMV) + LNEPS);

    float hh[8];
    float* hp = &g_h[(size_t)tok * DIMV];
#pragma unroll
    for (int jq = 0; jq < 8; jq++) {
        int d = lane + 32 * jq;
        if (d < DIMV) {
            float ln = (v[jq] - mean) * inv * gamma[d] + beta[d];
            hh[jq] = v[jq] + ln;
            hp[d] = hh[jq];
        } else hh[jq] = 0.f;
    }

    if (DO_GATE)
        gate_from_regs(hh, gW, gb, Lnext, tok, lane);
}

// ------------------------- head ---------------------------------------------
__global__ void head_kernel(const float* __restrict__ hW,
                            const float* __restrict__ hb,
                            float* __restrict__ out) {
    int b = blockIdx.x;
    int tid = threadIdx.x;       // 256
    const float* hp = g_h + (size_t)b * SS * DIMV;
    float acc = 0.f;
    for (int i = tid; i < SS * DIMV; i += 256)
        acc += hp[i] * hW[i % DIMV];
    __shared__ float red[256];
    red[tid] = acc;
    __syncthreads();
    for (int s2 = 128; s2 > 0; s2 >>= 1) {
        if (tid < s2) red[tid] += red[tid + s2];
        __syncthreads();
    }
    if (tid == 0) {
        float z = red[0] * (1.0f / SS) + hb[0];
        out[b] = 1.0f / (1.0f + expf(-z));
    }
}

// ------------------------- launch -------------------------------------------
extern "C" void kernel_launch(void* const* d_in, const int* in_sizes, int n_in,
                              void* d_out, int out_size) {
    const float* x     = (const float*)d_in[0];
    const int*   step  = (const int*)  d_in[1];
    const float* roots = (const float*)d_in[2];
    const float* projW = (const float*)d_in[3];
    const float* gW    = (const float*)d_in[4];
    const float* gb    = (const float*)d_in[5];
    const float* eW    = (const float*)d_in[6];
    const float* ebias = (const float*)d_in[7];
    const float* gamma = (const float*)d_in[8];
    const float* beta  = (const float*)d_in[9];
    const float* hW    = (const float*)d_in[10];
    const float* hb    = (const float*)d_in[11];
    float* out = (float*)d_out;

    setup_kernel<<<240, DIMV>>>(roots, projW);
    cycle_kernel<<<NTOK, DIMV>>>(x, step);
    gate_kernel<<<NTOK / 8, 256>>>(gW, gb, 0);

    dim3 gg(NTOK / MT, NEXP);
    for (int L = 0; L < NDEPTH; L++) {
        moe_gemm_kernel<<<gg, 256>>>(eW + (size_t)L * NEXP * DIMV * DIMV, L);
        if (L + 1 < NDEPTH) {
            epi_gate_kernel<1><<<NTOK / 8, 256>>>(
                ebias + (size_t)L * NEXP * DIMV, gamma, beta,
                gW + (size_t)(L + 1) * DIMV * NEXP, gb + (size_t)(L + 1) * NEXP,
                L + 1);
        } else {
            epi_gate_kernel<0><<<NTOK / 8, 256>>>(
                ebias + (size_t)L * NEXP * DIMV, gamma, beta,
                gW, gb, 0);
        }
    }

    head_kernel<<<BB, 256>>>(hW, hb, out);
}

// round 5
// speedup vs baseline: 1.2779x; 1.2779x over previous
#include <cuda_runtime.h>
#include <cuda_bf16.h>
#include <math.h>

#define BB 8
#define SS 2048
#define DIMV 240
#define NTOK (BB*SS)          // 16384
#define NEXP 8
#define NDEPTH 8
#define LATENTV 8
#define LOWD 80
#define LNEPS 1e-5f
#define PI_F 3.14159265358979323846f

// ------------------------- device scratch ----------------------------------
__device__ float g_h[(size_t)NTOK * DIMV];
__device__ float g_part[2][(size_t)NTOK * DIMV];
__device__ int   g_cnt[NDEPTH][NEXP];
__device__ int   g_list_tok[NEXP][NTOK];
__device__ float g_list_w[NEXP][NTOK];
__device__ int   g_list_k[NEXP][NTOK];
__device__ int   g_route_e[NTOK * 2];
__device__ float g_route_w[NTOK * 2];
__device__ float g_ce[240 * DIMV];
__device__ float g_se[240 * DIMV];

// ------------------------- f32x2 / cp.async helpers -------------------------
__device__ __forceinline__ void fma2(unsigned long long &d,
                                     unsigned long long a,
                                     unsigned long long b) {
    asm("fma.rn.f32x2 %0, %1, %2, %0;" : "+l"(d) : "l"(a), "l"(b));
}
__device__ __forceinline__ unsigned long long pack2(float a) {
    unsigned long long r;
    asm("mov.b64 %0, {%1, %1};" : "=l"(r) : "f"(a));
    return r;
}
__device__ __forceinline__ void unpack2(unsigned long long v, float &lo, float &hi) {
    asm("mov.b64 {%0, %1}, %2;" : "=f"(lo), "=f"(hi) : "l"(v));
}
__device__ __forceinline__ unsigned smem_u32(const void* p) {
    return (unsigned)__cvta_generic_to_shared(p);
}
__device__ __forceinline__ void cp16(unsigned dst, const void* src) {
    asm volatile("cp.async.ca.shared.global [%0], [%1], 16;\n"
                 :: "r"(dst), "l"(src));
}
__device__ __forceinline__ void cp_commit() {
    asm volatile("cp.async.commit_group;\n" ::: "memory");
}
template<int N>
__device__ __forceinline__ void cp_wait() {
    asm volatile("cp.async.wait_group %0;\n" :: "n"(N) : "memory");
}

// ------------------------- setup: emb tables + counter zero -----------------
__global__ void setup_kernel(const float* __restrict__ roots,
                             const float* __restrict__ projW) {
    int s = blockIdx.x;
    int d = threadIdx.x;
    int j = d % LOWD;
    float emb = 0.f;
#pragma unroll
    for (int i = 0; i < LATENTV; i++)
        emb += roots[s * LATENTV + i] * projW[i * LOWD + j];
    g_ce[s * DIMV + d] = cosf(emb);
    g_se[s * DIMV + d] = sinf(emb);
    if (blockIdx.x == 0 && d < NDEPTH * NEXP)
        ((int*)g_cnt)[d] = 0;
}

// ------------------------- cycle block --------------------------------------
__global__ void cycle_kernel(const float* __restrict__ x,
                             const int* __restrict__ step) {
    __shared__ float s_x1[DIMV];
    __shared__ float s_se[DIMV];
    __shared__ float s_pump;
    int t = blockIdx.x;
    int d = threadIdx.x;
    int r = (t % SS) % 240;
    if (d == 0) s_pump = 0.8f * sinf((float)(*step) * 0.006f * 2.0f * PI_F);
    float ce = g_ce[r * DIMV + d];
    float se = g_se[r * DIMV + d];
    s_se[d] = se;
    __syncthreads();
    float x1 = x[(size_t)t * DIMV + d] * (ce + s_pump);
    s_x1[d] = x1;
    __syncthreads();
    int dm1 = (d + DIMV - 1) % DIMV;
    int dm2 = (d + DIMV - 2) % DIMV;
    float h = (s_x1[d]
             + s_x1[dm1] * se
             + s_x1[dm2] * s_se[dm1] * ce) * (1.0f / 3.0f);
    g_h[(size_t)t * DIMV + d] = h;
}

// ------------------------- gate helper (warp; h in registers) ---------------
__device__ __forceinline__ void gate_from_regs(const float hh[8],
                                               const float* __restrict__ gW,
                                               const float* __restrict__ gb,
                                               int L, int tok, int lane) {
    float acc[8];
#pragma unroll
    for (int e = 0; e < 8; e++) acc[e] = 0.f;
#pragma unroll
    for (int jq = 0; jq < 8; jq++) {
        int d = lane + 32 * jq;
        if (d < DIMV) {
            float hv = hh[jq];
            float4 w0 = *(const float4*)&gW[d * 8];
            float4 w1 = *(const float4*)&gW[d * 8 + 4];
            acc[0] += hv * w0.x; acc[1] += hv * w0.y;
            acc[2] += hv * w0.z; acc[3] += hv * w0.w;
            acc[4] += hv * w1.x; acc[5] += hv * w1.y;
            acc[6] += hv * w1.z; acc[7] += hv * w1.w;
        }
    }
#pragma unroll
    for (int e = 0; e < 8; e++)
#pragma unroll
        for (int o = 16; o > 0; o >>= 1)
            acc[e] += __shfl_xor_sync(0xffffffffu, acc[e], o);

    if (lane == 0) {
        float l[8];
#pragma unroll
        for (int e = 0; e < 8; e++) l[e] = acc[e] + gb[e];
        int e0 = 0; float b0 = l[0];
#pragma unroll
        for (int q = 1; q < 8; q++)
            if (l[q] > b0) { b0 = l[q]; e0 = q; }
        int e1 = -1; float b1 = -1e30f;
#pragma unroll
        for (int q = 0; q < 8; q++)
            if (q != e0 && l[q] > b1) { b1 = l[q]; e1 = q; }

        float w0 = 1.0f / (1.0f + expf(b1 - b0));
        float w1 = 1.0f - w0;

        int p0 = atomicAdd(&g_cnt[L][e0], 1);
        g_list_tok[e0][p0] = tok; g_list_w[e0][p0] = w0; g_list_k[e0][p0] = 0;
        int p1 = atomicAdd(&g_cnt[L][e1], 1);
        g_list_tok[e1][p1] = tok; g_list_w[e1][p1] = w1; g_list_k[e1][p1] = 1;

        g_route_e[tok * 2 + 0] = e0; g_route_e[tok * 2 + 1] = e1;
        g_route_w[tok * 2 + 0] = w0; g_route_w[tok * 2 + 1] = w1;
    }
}

// ------------------------- gate from g_h (layer 0) ---------------------------
__global__ void gate_kernel(const float* __restrict__ gW,
                            const float* __restrict__ gb, int L) {
    int warp = threadIdx.x >> 5;
    int lane = threadIdx.x & 31;
    int tok  = blockIdx.x * 8 + warp;
    const float* h = g_h + (size_t)tok * DIMV;
    float hh[8];
#pragma unroll
    for (int jq = 0; jq < 8; jq++) {
        int d = lane + 32 * jq;
        hh[jq] = (d < DIMV) ? h[d] : 0.f;
    }
    gate_from_regs(hh, gW, gb, L, tok, lane);
}

// ------------------------- grouped expert GEMM ------------------------------
// Flattened tiles across experts; MT=64 tokens x 240 cols; 256 threads,
// 4 rows x 8 col-pairs per thread; cp.async double-buffered A and B.
#define MT 64
#define NTILES (2 * NTOK / MT + NEXP)   // 520 upper bound
__global__ __launch_bounds__(256, 2)
void moe_gemm_kernel(const float* __restrict__ eW, int L) {
    // ---- map flattened tile id -> (expert, base) ----
    int tileid = blockIdx.x;
    int e = 0, base = 0, cnt = 0;
    {
        int cum = 0;
        int cc[NEXP];
#pragma unroll
        for (int q = 0; q < NEXP; q++) cc[q] = g_cnt[L][q];
#pragma unroll
        for (int q = 0; q < NEXP; q++) {
            int t = (cc[q] + MT - 1) / MT;
            if (tileid >= cum && tileid < cum + t) {
                e = q; base = (tileid - cum) * MT; cnt = cc[q];
            }
            cum += t;
        }
        if (tileid >= cum) return;
    }
    int mr = min(MT, cnt - base);

    __shared__ __align__(16) float As[2][MT][20];    // [stage][token][k] (pad 20)
    __shared__ __align__(16) float Bs[2][16][256];   // [stage][k][col]
    __shared__ int   s_tok[MT];
    __shared__ float s_w[MT];
    __shared__ int   s_k[MT];

    int tid = threadIdx.x;
    if (tid < MT) {
        if (tid < mr) {
            s_tok[tid] = g_list_tok[e][base + tid];
            s_w[tid]   = g_list_w[e][base + tid];
            s_k[tid]   = g_list_k[e][base + tid];
        } else {
            s_tok[tid] = g_list_tok[e][base];   // clamp (masked at store)
            s_w[tid]   = 0.f;
            s_k[tid]   = 0;
        }
    }
    // zero pad cols 240..255 of both B stages (never touched by cp.async)
    {
        int rr = tid >> 4, c = tid & 15;
        Bs[0][rr][240 + c] = 0.f;
        Bs[1][rr][240 + c] = 0.f;
    }
    __syncthreads();

    const float* W = eW + (size_t)e * DIMV * DIMV;

    // per-thread cp.async assignments
    int a_rr = tid >> 2;                // 0..63
    int a_c4 = (tid & 3) * 4;           // 0,4,8,12
    const float* a_src_row = &g_h[(size_t)s_tok[a_rr] * DIMV + a_c4];

    // issue stage for k-slice `ks` into buffer `b`
    auto issue = [&](int ks, int b) {
        int k0 = ks * 16;
        cp16(smem_u32(&As[b][a_rr][a_c4]), a_src_row + k0);
#pragma unroll
        for (int j = 0; j < 4; j++) {
            int i = tid + j * 256;
            if (i < 960) {
                int rr = i / 60, cc2 = i - rr * 60;
                cp16(smem_u32(&Bs[b][rr][cc2 * 4]),
                     &W[(size_t)(k0 + rr) * DIMV + cc2 * 4]);
            }
        }
        cp_commit();
    };

    int tx = tid & 15;                  // col-pair group
    int ty = tid >> 4;                  // row group (rows ty*4..ty*4+3)

    unsigned long long acc[4][8];
#pragma unroll
    for (int i = 0; i < 4; i++)
#pragma unroll
        for (int jq = 0; jq < 8; jq++) acc[i][jq] = 0ull;

    issue(0, 0);

    for (int it = 0; it < 15; it++) {
        int buf = it & 1;
        if (it + 1 < 15) {
            issue(it + 1, buf ^ 1);
            cp_wait<1>();
        } else {
            cp_wait<0>();
        }
        __syncthreads();

#pragma unroll
        for (int dk = 0; dk < 16; dk++) {
            unsigned long long a2[4];
#pragma unroll
            for (int i = 0; i < 4; i++)
                a2[i] = pack2(As[buf][ty * 4 + i][dk]);
            unsigned long long bv[8];
#pragma unroll
            for (int jq = 0; jq < 8; jq++)
                bv[jq] = *(const unsigned long long*)&Bs[buf][dk][(tx + 16 * jq) * 2];
#pragma unroll
            for (int i = 0; i < 4; i++)
#pragma unroll
                for (int jq = 0; jq < 8; jq++)
                    fma2(acc[i][jq], a2[i], bv[jq]);
        }
        __syncthreads();
    }

#pragma unroll
    for (int i = 0; i < 4; i++) {
        int rr = ty * 4 + i;
        if (rr < mr) {
            float w = s_w[rr];
            float* dst = &g_part[s_k[rr]][(size_t)s_tok[rr] * DIMV];
#pragma unroll
            for (int jq = 0; jq < 8; jq++) {
                int P = tx + 16 * jq;
                if (P < 120) {
                    float lo, hi;
                    unpack2(acc[i][jq], lo, hi);
                    float2 o; o.x = w * lo; o.y = w * hi;
                    *(float2*)&dst[2 * P] = o;
                }
            }
        }
    }
}

// ------------- fused: epilogue(L) [+ gate(L+1) if DO_GATE] -------------------
template<int DO_GATE>
__global__ void epi_gate_kernel(const float* __restrict__ eb,
                                const float* __restrict__ gamma,
                                const float* __restrict__ beta,
                                const float* __restrict__ gW,
                                const float* __restrict__ gb,
                                int Lnext) {
    int warp = threadIdx.x >> 5;
    int lane = threadIdx.x & 31;
    int tok  = blockIdx.x * 8 + warp;

    int   e0 = g_route_e[tok * 2 + 0], e1 = g_route_e[tok * 2 + 1];
    float w0 = g_route_w[tok * 2 + 0], w1 = g_route_w[tok * 2 + 1];

    const float* p0 = &g_part[0][(size_t)tok * DIMV];
    const float* p1 = &g_part[1][(size_t)tok * DIMV];

    float v[8];
    float sum = 0.f;
#pragma unroll
    for (int jq = 0; jq < 8; jq++) {
        int d = lane + 32 * jq;
        if (d < DIMV) {
            v[jq] = p0[d] + p1[d] + w0 * eb[e0 * DIMV + d] + w1 * eb[e1 * DIMV + d];
            sum += v[jq];
        } else v[jq] = 0.f;
    }
#pragma unroll
    for (int o = 16; o > 0; o >>= 1) sum += __shfl_xor_sync(0xffffffffu, sum, o);
    float mean = sum * (1.0f / DIMV);

    float vs = 0.f;
#pragma unroll
    for (int jq = 0; jq < 8; jq++) {
        int d = lane + 32 * jq;
        if (d < DIMV) { float c = v[jq] - mean; vs += c * c; }
    }
#pragma unroll
    for (int o = 16; o > 0; o >>= 1) vs += __shfl_xor_sync(0xffffffffu, vs, o);
    float inv = 1.0f / sqrtf(vs * (1.0f / DIMV) + LNEPS);

    float hh[8];
    float* hp = &g_h[(size_t)tok * DIMV];
#pragma unroll
    for (int jq = 0; jq < 8; jq++) {
        int d = lane + 32 * jq;
        if (d < DIMV) {
            float ln = (v[jq] - mean) * inv * gamma[d] + beta[d];
            hh[jq] = v[jq] + ln;
            hp[d] = hh[jq];
        } else hh[jq] = 0.f;
    }

    if (DO_GATE)
        gate_from_regs(hh, gW, gb, Lnext, tok, lane);
}

// ------------------------- head ---------------------------------------------
__global__ void head_kernel(const float* __restrict__ hW,
                            const float* __restrict__ hb,
                            float* __restrict__ out) {
    int b = blockIdx.x;
    int tid = threadIdx.x;
    const float* hp = g_h + (size_t)b * SS * DIMV;
    float acc = 0.f;
    for (int i = tid; i < SS * DIMV; i += 256)
        acc += hp[i] * hW[i % DIMV];
    __shared__ float red[256];
    red[tid] = acc;
    __syncthreads();
    for (int s2 = 128; s2 > 0; s2 >>= 1) {
        if (tid < s2) red[tid] += red[tid + s2];
        __syncthreads();
    }
    if (tid == 0) {
        float z = red[0] * (1.0f / SS) + hb[0];
        out[b] = 1.0f / (1.0f + expf(-z));
    }
}

// ------------------------- launch -------------------------------------------
extern "C" void kernel_launch(void* const* d_in, const int* in_sizes, int n_in,
                              void* d_out, int out_size) {
    const float* x     = (const float*)d_in[0];
    const int*   step  = (const int*)  d_in[1];
    const float* roots = (const float*)d_in[2];
    const float* projW = (const float*)d_in[3];
    const float* gW    = (const float*)d_in[4];
    const float* gb    = (const float*)d_in[5];
    const float* eW    = (const float*)d_in[6];
    const float* ebias = (const float*)d_in[7];
    const float* gamma = (const float*)d_in[8];
    const float* beta  = (const float*)d_in[9];
    const float* hW    = (const float*)d_in[10];
    const float* hb    = (const float*)d_in[11];
    float* out = (float*)d_out;

    setup_kernel<<<240, DIMV>>>(roots, projW);
    cycle_kernel<<<NTOK, DIMV>>>(x, step);
    gate_kernel<<<NTOK / 8, 256>>>(gW, gb, 0);

    for (int L = 0; L < NDEPTH; L++) {
        moe_gemm_kernel<<<NTILES, 256>>>(eW + (size_t)L * NEXP * DIMV * DIMV, L);
        if (L + 1 < NDEPTH) {
            epi_gate_kernel<1><<<NTOK / 8, 256>>>(
                ebias + (size_t)L * NEXP * DIMV, gamma, beta,
                gW + (size_t)(L + 1) * DIMV * NEXP, gb + (size_t)(L + 1) * NEXP,
                L + 1);
        } else {
            epi_gate_kernel<0><<<NTOK / 8, 256>>>(
                ebias + (size_t)L * NEXP * DIMV, gamma, beta,
                gW, gb, 0);
        }
    }

    head_kernel<<<BB, 256>>>(hW, hb, out);
}

// round 7
// speedup vs baseline: 1.6505x; 1.2916x over previous
#include <cuda_runtime.h>
#include <cuda_bf16.h>
#include <math.h>
#include <stdint.h>

#define BB 8
#define SS 2048
#define DIMV 240
#define NTOK (BB*SS)          // 16384
#define NEXP 8
#define NDEPTH 8
#define LATENTV 8
#define LOWD 80
#define LNEPS 1e-5f
#define PI_F 3.14159265358979323846f

// ------------------------- device scratch ----------------------------------
__device__ float g_h[(size_t)NTOK * DIMV];
__device__ __nv_bfloat16 g_hh[(size_t)NTOK * DIMV];   // h hi (bf16)
__device__ __nv_bfloat16 g_hl[(size_t)NTOK * DIMV];   // h lo (bf16 residual)
__device__ float g_part[2][(size_t)NTOK * DIMV];
__device__ int   g_cnt[NDEPTH][NEXP];
__device__ int   g_list_tok[NEXP][NTOK];
__device__ float g_list_w[NEXP][NTOK];
__device__ int   g_list_k[NEXP][NTOK];
__device__ int   g_route_e[NTOK * 2];
__device__ float g_route_w[NTOK * 2];
__device__ float g_ce[240 * DIMV];
__device__ float g_se[240 * DIMV];
// transposed bf16 weight images: Bt[n][k] per (L,e)
__device__ __nv_bfloat16 g_Bth[(size_t)NDEPTH * NEXP * DIMV * DIMV];
__device__ __nv_bfloat16 g_Btl[(size_t)NDEPTH * NEXP * DIMV * DIMV];

// ------------------------- PTX helpers --------------------------------------
__device__ __forceinline__ unsigned smem_u32(const void* p) {
    return (unsigned)__cvta_generic_to_shared(p);
}
__device__ __forceinline__ void cp16(unsigned dst, const void* src) {
    asm volatile("cp.async.ca.shared.global [%0], [%1], 16;\n" :: "r"(dst), "l"(src));
}
__device__ __forceinline__ void cp_commit() {
    asm volatile("cp.async.commit_group;\n" ::: "memory");
}
template<int N>
__device__ __forceinline__ void cp_wait() {
    asm volatile("cp.async.wait_group %0;\n" :: "n"(N) : "memory");
}
#define MMA_BF16(dd, A0, A1, A2, A3, B0, B1)                                   \
    asm volatile("mma.sync.aligned.m16n8k16.row.col.f32.bf16.bf16.f32 "        \
                 "{%0,%1,%2,%3},{%4,%5,%6,%7},{%8,%9},{%0,%1,%2,%3};"          \
                 : "+f"((dd)[0]), "+f"((dd)[1]), "+f"((dd)[2]), "+f"((dd)[3])  \
                 : "r"(A0), "r"(A1), "r"(A2), "r"(A3), "r"(B0), "r"(B1))

// ------------------------- setup: emb tables + counter zero -----------------
__global__ void setup_kernel(const float* __restrict__ roots,
                             const float* __restrict__ projW) {
    int s = blockIdx.x;
    int d = threadIdx.x;
    int j = d % LOWD;
    float emb = 0.f;
#pragma unroll
    for (int i = 0; i < LATENTV; i++)
        emb += roots[s * LATENTV + i] * projW[i * LOWD + j];
    g_ce[s * DIMV + d] = cosf(emb);
    g_se[s * DIMV + d] = sinf(emb);
    if (blockIdx.x == 0 && d < NDEPTH * NEXP)
        ((int*)g_cnt)[d] = 0;
}

// ------------------------- B convert + transpose (per launch) ----------------
// Bt[n][k] = eW[le][k][n] split into bf16 hi + residual lo.
__global__ void bconv_kernel(const float* __restrict__ eW) {
    int le = blockIdx.x;     // 0..63 = L*8+e
    const float* W = eW + (size_t)le * DIMV * DIMV;
    __nv_bfloat16* BH = g_Bth + (size_t)le * DIMV * DIMV;
    __nv_bfloat16* BL = g_Btl + (size_t)le * DIMV * DIMV;
    __shared__ float tile[16][241];
    for (int s = 0; s < 15; s++) {
        int k0 = s * 16;
        for (int i = threadIdx.x; i < 16 * 240; i += 256) {
            int kk = i / 240, n = i - kk * 240;
            tile[kk][n] = W[(size_t)(k0 + kk) * DIMV + n];
        }
        __syncthreads();
        for (int i = threadIdx.x; i < 240 * 16; i += 256) {
            int n = i >> 4, kk = i & 15;
            float v = tile[kk][n];
            __nv_bfloat16 h = __float2bfloat16(v);
            float r = v - __bfloat162float(h);
            BH[(size_t)n * DIMV + k0 + kk] = h;
            BL[(size_t)n * DIMV + k0 + kk] = __float2bfloat16(r);
        }
        __syncthreads();
    }
}

// ------------------------- cycle block --------------------------------------
__global__ void cycle_kernel(const float* __restrict__ x,
                             const int* __restrict__ step) {
    __shared__ float s_x1[DIMV];
    __shared__ float s_se[DIMV];
    __shared__ float s_pump;
    int t = blockIdx.x;
    int d = threadIdx.x;
    int r = (t % SS) % 240;
    if (d == 0) s_pump = 0.8f * sinf((float)(*step) * 0.006f * 2.0f * PI_F);
    float ce = g_ce[r * DIMV + d];
    float se = g_se[r * DIMV + d];
    s_se[d] = se;
    __syncthreads();
    float x1 = x[(size_t)t * DIMV + d] * (ce + s_pump);
    s_x1[d] = x1;
    __syncthreads();
    int dm1 = (d + DIMV - 1) % DIMV;
    int dm2 = (d + DIMV - 2) % DIMV;
    float h = (s_x1[d]
             + s_x1[dm1] * se
             + s_x1[dm2] * s_se[dm1] * ce) * (1.0f / 3.0f);
    g_h[(size_t)t * DIMV + d] = h;
    __nv_bfloat16 hh = __float2bfloat16(h);
    g_hh[(size_t)t * DIMV + d] = hh;
    g_hl[(size_t)t * DIMV + d] = __float2bfloat16(h - __bfloat162float(hh));
}

// ------------------------- gate helper (warp; h in registers) ---------------
__device__ __forceinline__ void gate_from_regs(const float hh[8],
                                               const float* __restrict__ gW,
                                               const float* __restrict__ gb,
                                               int L, int tok, int lane) {
    float acc[8];
#pragma unroll
    for (int e = 0; e < 8; e++) acc[e] = 0.f;
#pragma unroll
    for (int jq = 0; jq < 8; jq++) {
        int d = lane + 32 * jq;
        if (d < DIMV) {
            float hv = hh[jq];
            float4 w0 = *(const float4*)&gW[d * 8];
            float4 w1 = *(const float4*)&gW[d * 8 + 4];
            acc[0] += hv * w0.x; acc[1] += hv * w0.y;
            acc[2] += hv * w0.z; acc[3] += hv * w0.w;
            acc[4] += hv * w1.x; acc[5] += hv * w1.y;
            acc[6] += hv * w1.z; acc[7] += hv * w1.w;
        }
    }
#pragma unroll
    for (int e = 0; e < 8; e++)
#pragma unroll
        for (int o = 16; o > 0; o >>= 1)
            acc[e] += __shfl_xor_sync(0xffffffffu, acc[e], o);

    if (lane == 0) {
        float l[8];
#pragma unroll
        for (int e = 0; e < 8; e++) l[e] = acc[e] + gb[e];
        int e0 = 0; float b0 = l[0];
#pragma unroll
        for (int q = 1; q < 8; q++)
            if (l[q] > b0) { b0 = l[q]; e0 = q; }
        int e1 = -1; float b1 = -1e30f;
#pragma unroll
        for (int q = 0; q < 8; q++)
            if (q != e0 && l[q] > b1) { b1 = l[q]; e1 = q; }

        float w0 = 1.0f / (1.0f + expf(b1 - b0));
        float w1 = 1.0f - w0;

        int p0 = atomicAdd(&g_cnt[L][e0], 1);
        g_list_tok[e0][p0] = tok; g_list_w[e0][p0] = w0; g_list_k[e0][p0] = 0;
        int p1 = atomicAdd(&g_cnt[L][e1], 1);
        g_list_tok[e1][p1] = tok; g_list_w[e1][p1] = w1; g_list_k[e1][p1] = 1;

        g_route_e[tok * 2 + 0] = e0; g_route_e[tok * 2 + 1] = e1;
        g_route_w[tok * 2 + 0] = w0; g_route_w[tok * 2 + 1] = w1;
    }
}

// ------------------------- gate from g_h (layer 0) ---------------------------
__global__ void gate_kernel(const float* __restrict__ gW,
                            const float* __restrict__ gb, int L) {
    int warp = threadIdx.x >> 5;
    int lane = threadIdx.x & 31;
    int tok  = blockIdx.x * 8 + warp;
    const float* h = g_h + (size_t)tok * DIMV;
    float hh[8];
#pragma unroll
    for (int jq = 0; jq < 8; jq++) {
        int d = lane + 32 * jq;
        hh[jq] = (d < DIMV) ? h[d] : 0.f;
    }
    gate_from_regs(hh, gW, gb, L, tok, lane);
}

// ------------------------- tensor-core grouped GEMM (mma.sync bf16) ---------
// Tile 64 gathered tokens x 240 cols; K chunks of 48, double buffered.
// 8 warps: wm = wid&3 (16-row m-tile), wn = wid>>2 (120-col n-half).
#define MT 64
#define NTILES (2 * NTOK / MT + NEXP)   // 520
#define KC 48
#define AST 56                           // smem row stride in bf16 (112 B)
// dynamic smem layout (bytes)
#define OFF_AH 0                         // [2][64][56] bf16 = 14336
#define OFF_AL 14336
#define OFF_BH 28672                     // [2][240][56] bf16 = 53760
#define OFF_BL 82432
#define SMEM_DYN 136192

__global__ __launch_bounds__(256, 1)
void moe_mma_kernel(int L) {
    // ---- flattened tile -> (expert, base) ----
    int tileid = blockIdx.x;
    int e = 0, base = 0, cnt = 0, cum = 0;
#pragma unroll
    for (int q = 0; q < NEXP; q++) {
        int cq = g_cnt[L][q];
        int t = (cq + MT - 1) / MT;
        if (tileid >= cum && tileid < cum + t) { e = q; base = (tileid - cum) * MT; cnt = cq; }
        cum += t;
    }
    if (tileid >= cum) return;
    int mr = min(MT, cnt - base);

    extern __shared__ __align__(16) char dsm[];
    __shared__ int   s_tok[MT];
    __shared__ float s_w[MT];
    __shared__ int   s_k[MT];

    int tid = threadIdx.x, wid = tid >> 5, lane = tid & 31;

    if (tid < MT) {
        if (tid < mr) {
            s_tok[tid] = g_list_tok[e][base + tid];
            s_w[tid]   = g_list_w[e][base + tid];
            s_k[tid]   = g_list_k[e][base + tid];
        } else { s_tok[tid] = 0; s_w[tid] = 0.f; s_k[tid] = 0; }
    }
    __syncthreads();

    const __nv_bfloat16* BHsrc = g_Bth + (size_t)(L * NEXP + e) * DIMV * DIMV;
    const __nv_bfloat16* BLsrc = g_Btl + (size_t)(L * NEXP + e) * DIMV * DIMV;

    // issue chunk kc into stage buf
    auto issue = [&](int kc, int buf) {
        int abuf = buf * (MT * AST * 2);
        int bbuf = buf * (DIMV * AST * 2);
        // A: 64 rows x 48 k = 6 x 16B per row per image
        for (int i = tid; i < MT * 6; i += 256) {
            int row = i / 6, seg = i - row * 6;
            size_t src = (size_t)s_tok[row] * DIMV + kc * KC + seg * 8;
            unsigned dst = (row * AST + seg * 8) * 2;
            cp16(smem_u32(dsm + OFF_AH + abuf + dst), g_hh + src);
            cp16(smem_u32(dsm + OFF_AL + abuf + dst), g_hl + src);
        }
        // B: 240 rows x 48 k
        for (int i = tid; i < DIMV * 6; i += 256) {
            int row = i / 6, seg = i - row * 6;
            size_t src = (size_t)row * DIMV + kc * KC + seg * 8;
            unsigned dst = (row * AST + seg * 8) * 2;
            cp16(smem_u32(dsm + OFF_BH + bbuf + dst), BHsrc + src);
            cp16(smem_u32(dsm + OFF_BL + bbuf + dst), BLsrc + src);
        }
        cp_commit();
    };

    int wm = wid & 3;     // m-tile (16 rows)
    int wn = wid >> 2;    // n-half (120 cols)

    float acc[15][4];
#pragma unroll
    for (int nt = 0; nt < 15; nt++)
#pragma unroll
        for (int j = 0; j < 4; j++) acc[nt][j] = 0.f;

    issue(0, 0);

    int aoff_base = ((wm * 16 + (lane >> 2)) * AST + (lane & 3) * 2) * 2;
    int boff_lane = ((lane >> 2)) * AST * 2 + (lane & 3) * 4;

    for (int kc = 0; kc < 5; kc++) {
        int buf = kc & 1;
        if (kc + 1 < 5) { issue(kc + 1, buf ^ 1); cp_wait<1>(); }
        else            { cp_wait<0>(); }
        __syncthreads();

        const char* Ah = dsm + OFF_AH + buf * (MT * AST * 2);
        const char* Al = dsm + OFF_AL + buf * (MT * AST * 2);
        const char* Bh = dsm + OFF_BH + buf * (DIMV * AST * 2);
        const char* Bl = dsm + OFF_BL + buf * (DIMV * AST * 2);

#pragma unroll
        for (int ks = 0; ks < 3; ks++) {
            int ako = aoff_base + ks * 32;
            uint32_t ah0 = *(const uint32_t*)(Ah + ako);
            uint32_t ah1 = *(const uint32_t*)(Ah + ako + 8 * AST * 2);
            uint32_t ah2 = *(const uint32_t*)(Ah + ako + 16);
            uint32_t ah3 = *(const uint32_t*)(Ah + ako + 8 * AST * 2 + 16);
            uint32_t al0 = *(const uint32_t*)(Al + ako);
            uint32_t al1 = *(const uint32_t*)(Al + ako + 8 * AST * 2);
            uint32_t al2 = *(const uint32_t*)(Al + ako + 16);
            uint32_t al3 = *(const uint32_t*)(Al + ako + 8 * AST * 2 + 16);
#pragma unroll
            for (int nt = 0; nt < 15; nt++) {
                int bko = (wn * 120 + nt * 8) * AST * 2 + boff_lane + ks * 32;
                uint32_t bh0 = *(const uint32_t*)(Bh + bko);
                uint32_t bh1 = *(const uint32_t*)(Bh + bko + 16);
                uint32_t bl0 = *(const uint32_t*)(Bl + bko);
                uint32_t bl1 = *(const uint32_t*)(Bl + bko + 16);
                MMA_BF16(acc[nt], ah0, ah1, ah2, ah3, bh0, bh1);
                MMA_BF16(acc[nt], ah0, ah1, ah2, ah3, bl0, bl1);
                MMA_BF16(acc[nt], al0, al1, al2, al3, bh0, bh1);
            }
        }
        __syncthreads();
    }

    // ---- scaled stores straight from fragments ----
    int r0 = wm * 16 + (lane >> 2);
    int r1 = r0 + 8;
    int colb = wn * 120 + (lane & 3) * 2;
    bool ok0 = r0 < mr, ok1 = r1 < mr;
    float w0v = s_w[r0], w1v = s_w[r1];
    float* d0 = ok0 ? &g_part[s_k[r0]][(size_t)s_tok[r0] * DIMV] : 0;
    float* d1 = ok1 ? &g_part[s_k[r1]][(size_t)s_tok[r1] * DIMV] : 0;
#pragma unroll
    for (int nt = 0; nt < 15; nt++) {
        int col = colb + nt * 8;
        if (ok0) {
            float2 o; o.x = w0v * acc[nt][0]; o.y = w0v * acc[nt][1];
            *(float2*)&d0[col] = o;
        }
        if (ok1) {
            float2 o; o.x = w1v * acc[nt][2]; o.y = w1v * acc[nt][3];
            *(float2*)&d1[col] = o;
        }
    }
}

// ------------- fused: epilogue(L) [+ gate(L+1) if DO_GATE] -------------------
template<int DO_GATE>
__global__ void epi_gate_kernel(const float* __restrict__ eb,
                                const float* __restrict__ gamma,
                                const float* __restrict__ beta,
                                const float* __restrict__ gW,
                                const float* __restrict__ gb,
                                int Lnext) {
    int warp = threadIdx.x >> 5;
    int lane = threadIdx.x & 31;
    int tok  = blockIdx.x * 8 + warp;

    int   e0 = g_route_e[tok * 2 + 0], e1 = g_route_e[tok * 2 + 1];
    float w0 = g_route_w[tok * 2 + 0], w1 = g_route_w[tok * 2 + 1];

    const float* p0 = &g_part[0][(size_t)tok * DIMV];
    const float* p1 = &g_part[1][(size_t)tok * DIMV];

    float v[8];
    float sum = 0.f;
#pragma unroll
    for (int jq = 0; jq < 8; jq++) {
        int d = lane + 32 * jq;
        if (d < DIMV) {
            v[jq] = p0[d] + p1[d] + w0 * eb[e0 * DIMV + d] + w1 * eb[e1 * DIMV + d];
            sum += v[jq];
        } else v[jq] = 0.f;
    }
#pragma unroll
    for (int o = 16; o > 0; o >>= 1) sum += __shfl_xor_sync(0xffffffffu, sum, o);
    float mean = sum * (1.0f / DIMV);

    float vs = 0.f;
#pragma unroll
    for (int jq = 0; jq < 8; jq++) {
        int d = lane + 32 * jq;
        if (d < DIMV) { float c = v[jq] - mean; vs += c * c; }
    }
#pragma unroll
    for (int o = 16; o > 0; o >>= 1) vs += __shfl_xor_sync(0xffffffffu, vs, o);
    float inv = 1.0f / sqrtf(vs * (1.0f / DIMV) + LNEPS);

    float hh[8];
    float* hp = &g_h[(size_t)tok * DIMV];
    __nv_bfloat16* hph = &g_hh[(size_t)tok * DIMV];
    __nv_bfloat16* hpl = &g_hl[(size_t)tok * DIMV];
#pragma unroll
    for (int jq = 0; jq < 8; jq++) {
        int d = lane + 32 * jq;
        if (d < DIMV) {
            float ln = (v[jq] - mean) * inv * gamma[d] + beta[d];
            float hv = v[jq] + ln;
            hh[jq] = hv;
            hp[d] = hv;
            __nv_bfloat16 hi = __float2bfloat16(hv);
            hph[d] = hi;
            hpl[d] = __float2bfloat16(hv - __bfloat162float(hi));
        } else hh[jq] = 0.f;
    }

    if (DO_GATE)
        gate_from_regs(hh, gW, gb, Lnext, tok, lane);
}

// ------------------------- head ---------------------------------------------
__global__ void head_kernel(const float* __restrict__ hW,
                            const float* __restrict__ hb,
                            float* __restrict__ out) {
    int b = blockIdx.x;
    int tid = threadIdx.x;
    const float* hp = g_h + (size_t)b * SS * DIMV;
    float acc = 0.f;
    for (int i = tid; i < SS * DIMV; i += 256)
        acc += hp[i] * hW[i % DIMV];
    __shared__ float red[256];
    red[tid] = acc;
    __syncthreads();
    for (int s2 = 128; s2 > 0; s2 >>= 1) {
        if (tid < s2) red[tid] += red[tid + s2];
        __syncthreads();
    }
    if (tid == 0) {
        float z = red[0] * (1.0f / SS) + hb[0];
        out[b] = 1.0f / (1.0f + expf(-z));
    }
}

// ------------------------- launch -------------------------------------------
extern "C" void kernel_launch(void* const* d_in, const int* in_sizes, int n_in,
                              void* d_out, int out_size) {
    const float* x     = (const float*)d_in[0];
    const int*   step  = (const int*)  d_in[1];
    const float* roots = (const float*)d_in[2];
    const float* projW = (const float*)d_in[3];
    const float* gW    = (const float*)d_in[4];
    const float* gb    = (const float*)d_in[5];
    const float* eW    = (const float*)d_in[6];
    const float* ebias = (const float*)d_in[7];
    const float* gamma = (const float*)d_in[8];
    const float* beta  = (const float*)d_in[9];
    const float* hW    = (const float*)d_in[10];
    const float* hb    = (const float*)d_in[11];
    float* out = (float*)d_out;

    cudaFuncSetAttribute(moe_mma_kernel,
                         cudaFuncAttributeMaxDynamicSharedMemorySize, SMEM_DYN);

    setup_kernel<<<240, DIMV>>>(roots, projW);
    bconv_kernel<<<NDEPTH * NEXP, 256>>>(eW);
    cycle_kernel<<<NTOK, DIMV>>>(x, step);
    gate_kernel<<<NTOK / 8, 256>>>(gW, gb, 0);

    for (int L = 0; L < NDEPTH; L++) {
        moe_mma_kernel<<<NTILES, 256, SMEM_DYN>>>(L);
        if (L + 1 < NDEPTH) {
            epi_gate_kernel<1><<<NTOK / 8, 256>>>(
                ebias + (size_t)L * NEXP * DIMV, gamma, beta,
                gW + (size_t)(L + 1) * DIMV * NEXP, gb + (size_t)(L + 1) * NEXP,
                L + 1);
        } else {
            epi_gate_kernel<0><<<NTOK / 8, 256>>>(
                ebias + (size_t)L * NEXP * DIMV, gamma, beta,
                gW, gb, 0);
        }
    }

    head_kernel<<<BB, 256>>>(hW, hb, out);
}

// round 8
// speedup vs baseline: 1.7605x; 1.0666x over previous
#include <cuda_runtime.h>
#include <cuda_bf16.h>
#include <math.h>
#include <stdint.h>

#define BB 8
#define SS 2048
#define DIMV 240
#define NTOK (BB*SS)          // 16384
#define NEXP 8
#define NDEPTH 8
#define LATENTV 8
#define LOWD 80
#define LNEPS 1e-5f
#define PI_F 3.14159265358979323846f

// ------------------------- device scratch ----------------------------------
__device__ __nv_bfloat16 g_hh[(size_t)NTOK * DIMV];   // h hi (bf16)
__device__ __nv_bfloat16 g_hl[(size_t)NTOK * DIMV];   // h lo (bf16 residual)
__device__ float g_part[2][(size_t)NTOK * DIMV];
__device__ int   g_cnt[NDEPTH][NEXP];
__device__ int   g_list_tok[NEXP][NTOK];
__device__ float g_list_w[NEXP][NTOK];
__device__ int   g_list_k[NEXP][NTOK];
__device__ int   g_route_e[NTOK * 2];
__device__ float g_route_w[NTOK * 2];
__device__ float g_ce[240 * DIMV];
__device__ float g_se[240 * DIMV];
__device__ __nv_bfloat16 g_Bth[(size_t)NDEPTH * NEXP * DIMV * DIMV];
__device__ __nv_bfloat16 g_Btl[(size_t)NDEPTH * NEXP * DIMV * DIMV];

// ------------------------- PTX helpers --------------------------------------
__device__ __forceinline__ unsigned smem_u32(const void* p) {
    return (unsigned)__cvta_generic_to_shared(p);
}
__device__ __forceinline__ void cp16(unsigned dst, const void* src) {
    asm volatile("cp.async.ca.shared.global [%0], [%1], 16;\n" :: "r"(dst), "l"(src));
}
__device__ __forceinline__ void cp_commit() {
    asm volatile("cp.async.commit_group;\n" ::: "memory");
}
template<int N>
__device__ __forceinline__ void cp_wait() {
    asm volatile("cp.async.wait_group %0;\n" :: "n"(N) : "memory");
}
#define MMA_BF16(dd, A0, A1, A2, A3, B0, B1)                                   \
    asm volatile("mma.sync.aligned.m16n8k16.row.col.f32.bf16.bf16.f32 "        \
                 "{%0,%1,%2,%3},{%4,%5,%6,%7},{%8,%9},{%0,%1,%2,%3};"          \
                 : "+f"((dd)[0]), "+f"((dd)[1]), "+f"((dd)[2]), "+f"((dd)[3])  \
                 : "r"(A0), "r"(A1), "r"(A2), "r"(A3), "r"(B0), "r"(B1))

// ------------------------- routing finalize (one thread) --------------------
__device__ __forceinline__ void route_finalize(const float l[8], int L, int tok) {
    int e0 = 0; float b0 = l[0];
#pragma unroll
    for (int q = 1; q < 8; q++)
        if (l[q] > b0) { b0 = l[q]; e0 = q; }
    int e1 = -1; float b1 = -1e30f;
#pragma unroll
    for (int q = 0; q < 8; q++)
        if (q != e0 && l[q] > b1) { b1 = l[q]; e1 = q; }

    float w0 = 1.0f / (1.0f + expf(b1 - b0));
    float w1 = 1.0f - w0;

    int p0 = atomicAdd(&g_cnt[L][e0], 1);
    g_list_tok[e0][p0] = tok; g_list_w[e0][p0] = w0; g_list_k[e0][p0] = 0;
    int p1 = atomicAdd(&g_cnt[L][e1], 1);
    g_list_tok[e1][p1] = tok; g_list_w[e1][p1] = w1; g_list_k[e1][p1] = 1;

    g_route_e[tok * 2 + 0] = e0; g_route_e[tok * 2 + 1] = e1;
    g_route_w[tok * 2 + 0] = w0; g_route_w[tok * 2 + 1] = w1;
}

// ------------------------- setup: emb tables + counter zero -----------------
__global__ void setup_kernel(const float* __restrict__ roots,
                             const float* __restrict__ projW) {
    int s = blockIdx.x;
    int d = threadIdx.x;
    int j = d % LOWD;
    float emb = 0.f;
#pragma unroll
    for (int i = 0; i < LATENTV; i++)
        emb += roots[s * LATENTV + i] * projW[i * LOWD + j];
    g_ce[s * DIMV + d] = cosf(emb);
    g_se[s * DIMV + d] = sinf(emb);
    if (blockIdx.x == 0 && d < NDEPTH * NEXP)
        ((int*)g_cnt)[d] = 0;
}

// ------------------------- B convert + transpose ----------------------------
// grid (15, 64): blockIdx.x = k-slice, blockIdx.y = L*8+e
__global__ void bconv_kernel(const float* __restrict__ eW) {
    int le = blockIdx.y;
    int k0 = blockIdx.x * 16;
    const float* W = eW + (size_t)le * DIMV * DIMV;
    __nv_bfloat16* BH = g_Bth + (size_t)le * DIMV * DIMV;
    __nv_bfloat16* BL = g_Btl + (size_t)le * DIMV * DIMV;
    __shared__ float tile[16][241];
    for (int i = threadIdx.x; i < 16 * 240; i += 256) {
        int kk = i / 240, n = i - kk * 240;
        tile[kk][n] = W[(size_t)(k0 + kk) * DIMV + n];
    }
    __syncthreads();
    for (int i = threadIdx.x; i < 240 * 16; i += 256) {
        int n = i >> 4, kk = i & 15;
        float v = tile[kk][n];
        __nv_bfloat16 h = __float2bfloat16(v);
        float r = v - __bfloat162float(h);
        BH[(size_t)n * DIMV + k0 + kk] = h;
        BL[(size_t)n * DIMV + k0 + kk] = __float2bfloat16(r);
    }
}

// ------------------------- cycle block + fused gate(0) ----------------------
// block = one token, 256 threads (d < 240 active for data)
__global__ void cycle_kernel(const float* __restrict__ x,
                             const int* __restrict__ step,
                             const float* __restrict__ gW,   // layer 0 [240,8]
                             const float* __restrict__ gb) { // [8]
    __shared__ float s_x1[DIMV];
    __shared__ float s_se[DIMV];
    __shared__ float s_pump;
    __shared__ float s_acc[8];
    int t = blockIdx.x;
    int d = threadIdx.x;
    int lane = d & 31;
    int r = (t % SS) % 240;
    if (d == 0) s_pump = 0.8f * sinf((float)(*step) * 0.006f * 2.0f * PI_F);
    if (d < 8) s_acc[d] = 0.f;
    float ce = 0.f, se = 0.f;
    if (d < DIMV) {
        ce = g_ce[r * DIMV + d];
        se = g_se[r * DIMV + d];
        s_se[d] = se;
    }
    __syncthreads();
    if (d < DIMV)
        s_x1[d] = x[(size_t)t * DIMV + d] * (ce + s_pump);
    __syncthreads();

    float h = 0.f;
    if (d < DIMV) {
        int dm1 = (d + DIMV - 1) % DIMV;
        int dm2 = (d + DIMV - 2) % DIMV;
        h = (s_x1[d]
           + s_x1[dm1] * se
           + s_x1[dm2] * s_se[dm1] * ce) * (1.0f / 3.0f);
        __nv_bfloat16 hi = __float2bfloat16(h);
        g_hh[(size_t)t * DIMV + d] = hi;
        g_hl[(size_t)t * DIMV + d] = __float2bfloat16(h - __bfloat162float(hi));
    }

    // fused gate for layer 0
    float p[8];
    if (d < DIMV) {
        float4 w0 = *(const float4*)&gW[d * 8];
        float4 w1 = *(const float4*)&gW[d * 8 + 4];
        p[0] = h * w0.x; p[1] = h * w0.y; p[2] = h * w0.z; p[3] = h * w0.w;
        p[4] = h * w1.x; p[5] = h * w1.y; p[6] = h * w1.z; p[7] = h * w1.w;
    } else {
#pragma unroll
        for (int e = 0; e < 8; e++) p[e] = 0.f;
    }
#pragma unroll
    for (int e = 0; e < 8; e++)
#pragma unroll
        for (int o = 16; o > 0; o >>= 1)
            p[e] += __shfl_xor_sync(0xffffffffu, p[e], o);
    if (lane == 0) {
#pragma unroll
        for (int e = 0; e < 8; e++)
            atomicAdd(&s_acc[e], p[e]);
    }
    __syncthreads();
    if (d == 0) {
        float l[8];
#pragma unroll
        for (int e = 0; e < 8; e++) l[e] = s_acc[e] + gb[e];
        route_finalize(l, 0, t);
    }
}

// ------------------------- gate helper (warp; h in registers) ---------------
__device__ __forceinline__ void gate_from_regs(const float hh[8],
                                               const float* __restrict__ gW,
                                               const float* __restrict__ gb,
                                               int L, int tok, int lane) {
    float acc[8];
#pragma unroll
    for (int e = 0; e < 8; e++) acc[e] = 0.f;
#pragma unroll
    for (int jq = 0; jq < 8; jq++) {
        int d = lane + 32 * jq;
        if (d < DIMV) {
            float hv = hh[jq];
            float4 w0 = *(const float4*)&gW[d * 8];
            float4 w1 = *(const float4*)&gW[d * 8 + 4];
            acc[0] += hv * w0.x; acc[1] += hv * w0.y;
            acc[2] += hv * w0.z; acc[3] += hv * w0.w;
            acc[4] += hv * w1.x; acc[5] += hv * w1.y;
            acc[6] += hv * w1.z; acc[7] += hv * w1.w;
        }
    }
#pragma unroll
    for (int e = 0; e < 8; e++)
#pragma unroll
        for (int o = 16; o > 0; o >>= 1)
            acc[e] += __shfl_xor_sync(0xffffffffu, acc[e], o);

    if (lane == 0) {
        float l[8];
#pragma unroll
        for (int e = 0; e < 8; e++) l[e] = acc[e] + gb[e];
        route_finalize(l, L, tok);
    }
}

// ------------------------- tensor-core grouped GEMM (mma.sync bf16) ---------
// Tile 128 gathered tokens x 240 cols; K chunks of 48, double buffered.
// 8 warps: wm = wid&3 (rows wm*32..wm*32+31, two 16-row m-tiles), wn = wid>>2.
#define MT 128
#define NTILES (2 * NTOK / MT + NEXP)   // 264
#define KC 48
#define AST 56                           // smem row stride in bf16 (112 B)
#define OFF_AH 0                         // [2][128][56] bf16 = 28672
#define OFF_AL 28672
#define OFF_BH 57344                     // [2][240][56] bf16 = 53760
#define OFF_BL 111104
#define SMEM_DYN 164864

__global__ __launch_bounds__(256, 1)
void moe_mma_kernel(int L) {
    int tileid = blockIdx.x;
    int e = 0, base = 0, cnt = 0, cum = 0;
#pragma unroll
    for (int q = 0; q < NEXP; q++) {
        int cq = g_cnt[L][q];
        int t = (cq + MT - 1) / MT;
        if (tileid >= cum && tileid < cum + t) { e = q; base = (tileid - cum) * MT; cnt = cq; }
        cum += t;
    }
    if (tileid >= cum) return;
    int mr = min(MT, cnt - base);

    extern __shared__ __align__(16) char dsm[];
    __shared__ int   s_tok[MT];
    __shared__ float s_w[MT];
    __shared__ int   s_k[MT];

    int tid = threadIdx.x, wid = tid >> 5, lane = tid & 31;

    if (tid < MT) {
        if (tid < mr) {
            s_tok[tid] = g_list_tok[e][base + tid];
            s_w[tid]   = g_list_w[e][base + tid];
            s_k[tid]   = g_list_k[e][base + tid];
        } else { s_tok[tid] = 0; s_w[tid] = 0.f; s_k[tid] = 0; }
    }
    __syncthreads();

    const __nv_bfloat16* BHsrc = g_Bth + (size_t)(L * NEXP + e) * DIMV * DIMV;
    const __nv_bfloat16* BLsrc = g_Btl + (size_t)(L * NEXP + e) * DIMV * DIMV;

    auto issue = [&](int kc, int buf) {
        int abuf = buf * (MT * AST * 2);
        int bbuf = buf * (DIMV * AST * 2);
#pragma unroll
        for (int j = 0; j < 3; j++) {                 // A: 128 rows x 6 segs = 768
            int i = tid + j * 256;
            int row = i / 6, seg = i - row * 6;
            size_t src = (size_t)s_tok[row] * DIMV + kc * KC + seg * 8;
            unsigned dst = (row * AST + seg * 8) * 2;
            cp16(smem_u32(dsm + OFF_AH + abuf + dst), g_hh + src);
            cp16(smem_u32(dsm + OFF_AL + abuf + dst), g_hl + src);
        }
        for (int i = tid; i < DIMV * 6; i += 256) {   // B: 240 rows x 6 segs
            int row = i / 6, seg = i - row * 6;
            size_t src = (size_t)row * DIMV + kc * KC + seg * 8;
            unsigned dst = (row * AST + seg * 8) * 2;
            cp16(smem_u32(dsm + OFF_BH + bbuf + dst), BHsrc + src);
            cp16(smem_u32(dsm + OFF_BL + bbuf + dst), BLsrc + src);
        }
        cp_commit();
    };

    int wm = wid & 3;
    int wn = wid >> 2;

    float acc[2][15][4];
#pragma unroll
    for (int t = 0; t < 2; t++)
#pragma unroll
        for (int nt = 0; nt < 15; nt++)
#pragma unroll
            for (int j = 0; j < 4; j++) acc[t][nt][j] = 0.f;

    issue(0, 0);

    int aoff0 = ((wm * 32 + (lane >> 2)) * AST + (lane & 3) * 2) * 2;
    int boff_lane = (lane >> 2) * AST * 2 + (lane & 3) * 4;

    for (int kc = 0; kc < 5; kc++) {
        int buf = kc & 1;
        if (kc + 1 < 5) { issue(kc + 1, buf ^ 1); cp_wait<1>(); }
        else            { cp_wait<0>(); }
        __syncthreads();

        const char* Ah = dsm + OFF_AH + buf * (MT * AST * 2);
        const char* Al = dsm + OFF_AL + buf * (MT * AST * 2);
        const char* Bh = dsm + OFF_BH + buf * (DIMV * AST * 2);
        const char* Bl = dsm + OFF_BL + buf * (DIMV * AST * 2);

#pragma unroll
        for (int ks = 0; ks < 3; ks++) {
            uint32_t ah[2][4], al[2][4];
#pragma unroll
            for (int t = 0; t < 2; t++) {
                int ako = aoff0 + t * 16 * AST * 2 + ks * 32;
                ah[t][0] = *(const uint32_t*)(Ah + ako);
                ah[t][1] = *(const uint32_t*)(Ah + ako + 8 * AST * 2);
                ah[t][2] = *(const uint32_t*)(Ah + ako + 16);
                ah[t][3] = *(const uint32_t*)(Ah + ako + 8 * AST * 2 + 16);
                al[t][0] = *(const uint32_t*)(Al + ako);
                al[t][1] = *(const uint32_t*)(Al + ako + 8 * AST * 2);
                al[t][2] = *(const uint32_t*)(Al + ako + 16);
                al[t][3] = *(const uint32_t*)(Al + ako + 8 * AST * 2 + 16);
            }
#pragma unroll
            for (int nt = 0; nt < 15; nt++) {
                int bko = (wn * 120 + nt * 8) * AST * 2 + boff_lane + ks * 32;
                uint32_t bh0 = *(const uint32_t*)(Bh + bko);
                uint32_t bh1 = *(const uint32_t*)(Bh + bko + 16);
                uint32_t bl0 = *(const uint32_t*)(Bl + bko);
                uint32_t bl1 = *(const uint32_t*)(Bl + bko + 16);
#pragma unroll
                for (int t = 0; t < 2; t++) {
                    MMA_BF16(acc[t][nt], ah[t][0], ah[t][1], ah[t][2], ah[t][3], bh0, bh1);
                    MMA_BF16(acc[t][nt], ah[t][0], ah[t][1], ah[t][2], ah[t][3], bl0, bl1);
                    MMA_BF16(acc[t][nt], al[t][0], al[t][1], al[t][2], al[t][3], bh0, bh1);
                }
            }
        }
        __syncthreads();
    }

    // ---- scaled stores straight from fragments ----
#pragma unroll
    for (int t = 0; t < 2; t++) {
        int r0 = wm * 32 + t * 16 + (lane >> 2);
        int r1 = r0 + 8;
        int colb = wn * 120 + (lane & 3) * 2;
        bool ok0 = r0 < mr, ok1 = r1 < mr;
        float w0v = s_w[r0], w1v = s_w[r1];
        float* d0 = ok0 ? &g_part[s_k[r0]][(size_t)s_tok[r0] * DIMV] : 0;
        float* d1 = ok1 ? &g_part[s_k[r1]][(size_t)s_tok[r1] * DIMV] : 0;
#pragma unroll
        for (int nt = 0; nt < 15; nt++) {
            int col = colb + nt * 8;
            if (ok0) {
                float2 o; o.x = w0v * acc[t][nt][0]; o.y = w0v * acc[t][nt][1];
                *(float2*)&d0[col] = o;
            }
            if (ok1) {
                float2 o; o.x = w1v * acc[t][nt][2]; o.y = w1v * acc[t][nt][3];
                *(float2*)&d1[col] = o;
            }
        }
    }
}

// ------------- fused: epilogue(L) [+ gate(L+1) if DO_GATE] -------------------
template<int DO_GATE>
__global__ void epi_gate_kernel(const float* __restrict__ eb,
                                const float* __restrict__ gamma,
                                const float* __restrict__ beta,
                                const float* __restrict__ gW,
                                const float* __restrict__ gb,
                                int Lnext) {
    int warp = threadIdx.x >> 5;
    int lane = threadIdx.x & 31;
    int tok  = blockIdx.x * 8 + warp;

    int   e0 = g_route_e[tok * 2 + 0], e1 = g_route_e[tok * 2 + 1];
    float w0 = g_route_w[tok * 2 + 0], w1 = g_route_w[tok * 2 + 1];

    const float* p0 = &g_part[0][(size_t)tok * DIMV];
    const float* p1 = &g_part[1][(size_t)tok * DIMV];

    float v[8];
    float sum = 0.f;
#pragma unroll
    for (int jq = 0; jq < 8; jq++) {
        int d = lane + 32 * jq;
        if (d < DIMV) {
            v[jq] = p0[d] + p1[d] + w0 * eb[e0 * DIMV + d] + w1 * eb[e1 * DIMV + d];
            sum += v[jq];
        } else v[jq] = 0.f;
    }
#pragma unroll
    for (int o = 16; o > 0; o >>= 1) sum += __shfl_xor_sync(0xffffffffu, sum, o);
    float mean = sum * (1.0f / DIMV);

    float vs = 0.f;
#pragma unroll
    for (int jq = 0; jq < 8; jq++) {
        int d = lane + 32 * jq;
        if (d < DIMV) { float c = v[jq] - mean; vs += c * c; }
    }
#pragma unroll
    for (int o = 16; o > 0; o >>= 1) vs += __shfl_xor_sync(0xffffffffu, vs, o);
    float inv = 1.0f / sqrtf(vs * (1.0f / DIMV) + LNEPS);

    float hh[8];
    __nv_bfloat16* hph = &g_hh[(size_t)tok * DIMV];
    __nv_bfloat16* hpl = &g_hl[(size_t)tok * DIMV];
#pragma unroll
    for (int jq = 0; jq < 8; jq++) {
        int d = lane + 32 * jq;
        if (d < DIMV) {
            float ln = (v[jq] - mean) * inv * gamma[d] + beta[d];
            float hv = v[jq] + ln;
            hh[jq] = hv;
            __nv_bfloat16 hi = __float2bfloat16(hv);
            hph[d] = hi;
            hpl[d] = __float2bfloat16(hv - __bfloat162float(hi));
        } else hh[jq] = 0.f;
    }

    if (DO_GATE)
        gate_from_regs(hh, gW, gb, Lnext, tok, lane);
}

// ------------------------- head (h = hi + lo) --------------------------------
__global__ void head_kernel(const float* __restrict__ hW,
                            const float* __restrict__ hb,
                            float* __restrict__ out) {
    int b = blockIdx.x;
    int tid = threadIdx.x;
    const __nv_bfloat16* hh = g_hh + (size_t)b * SS * DIMV;
    const __nv_bfloat16* hl = g_hl + (size_t)b * SS * DIMV;
    float acc = 0.f;
    for (int i = tid; i < SS * DIMV; i += 256) {
        float h = __bfloat162float(hh[i]) + __bfloat162float(hl[i]);
        acc += h * hW[i % DIMV];
    }
    __shared__ float red[256];
    red[tid] = acc;
    __syncthreads();
    for (int s2 = 128; s2 > 0; s2 >>= 1) {
        if (tid < s2) red[tid] += red[tid + s2];
        __syncthreads();
    }
    if (tid == 0) {
        float z = red[0] * (1.0f / SS) + hb[0];
        out[b] = 1.0f / (1.0f + expf(-z));
    }
}

// ------------------------- launch -------------------------------------------
extern "C" void kernel_launch(void* const* d_in, const int* in_sizes, int n_in,
                              void* d_out, int out_size) {
    const float* x     = (const float*)d_in[0];
    const int*   step  = (const int*)  d_in[1];
    const float* roots = (const float*)d_in[2];
    const float* projW = (const float*)d_in[3];
    const float* gW    = (const float*)d_in[4];
    const float* gb    = (const float*)d_in[5];
    const float* eW    = (const float*)d_in[6];
    const float* ebias = (const float*)d_in[7];
    const float* gamma = (const float*)d_in[8];
    const float* beta  = (const float*)d_in[9];
    const float* hW    = (const float*)d_in[10];
    const float* hb    = (const float*)d_in[11];
    float* out = (float*)d_out;

    cudaFuncSetAttribute(moe_mma_kernel,
                         cudaFuncAttributeMaxDynamicSharedMemorySize, SMEM_DYN);

    setup_kernel<<<240, DIMV>>>(roots, projW);
    {
        dim3 bg(15, NDEPTH * NEXP);
        bconv_kernel<<<bg, 256>>>(eW);
    }
    cycle_kernel<<<NTOK, 256>>>(x, step, gW, gb);

    for (int L = 0; L < NDEPTH; L++) {
        moe_mma_kernel<<<NTILES, 256, SMEM_DYN>>>(L);
        if (L + 1 < NDEPTH) {
            epi_gate_kernel<1><<<NTOK / 8, 256>>>(
                ebias + (size_t)L * NEXP * DIMV, gamma, beta,
                gW + (size_t)(L + 1) * DIMV * NEXP, gb + (size_t)(L + 1) * NEXP,
                L + 1);
        } else {
            epi_gate_kernel<0><<<NTOK / 8, 256>>>(
                ebias + (size_t)L * NEXP * DIMV, gamma, beta,
                gW, gb, 0);
        }
    }

    head_kernel<<<BB, 256>>>(hW, hb, out);
}